// round 10
// baseline (speedup 1.0000x reference)
#include <cuda_runtime.h>
#include <math.h>

#define NNODE 512
#define TT 12
#define DD 128
#define NROWS 1536            // 64*2*12 rows
#define EPSBN 1e-5f

// ---------------- device scratch ----------------
__device__ float g_Y0[NROWS * NNODE];        // x transposed
__device__ float g_Yh[NROWS * 2048];         // [row][(p-1)*512 + n], p=1..4
__device__ float g_B[NNODE * 2048];          // [v][A | A2 | A3 | A4]
__device__ float g_q[5 * NNODE];             // rows 1..4 used
__device__ float g_Sfin[10 * DD];            // [j=p*2+e][c]
__device__ float g_SkUf[DD * 5];             // [c][k], ob-scaled
__device__ float g_mo[DD];

// ---------------- f32x2 helpers ----------------
__device__ __forceinline__ unsigned long long pack2(float x, float y) {
    unsigned long long r;
    asm("mov.b64 %0, {%1, %2};" : "=l"(r) : "f"(x), "f"(y));
    return r;
}
__device__ __forceinline__ void fma2(unsigned long long& d,
                                     unsigned long long a, unsigned long long b) {
    asm("fma.rn.f32x2 %0, %1, %2, %3;" : "=l"(d) : "l"(a), "l"(b), "l"(d));
}
union F2U { unsigned long long u; float2 f; };

// ---------------- transpose x -> Y0 ----------------
__global__ void k_transpose(const float* __restrict__ x) {   // grid 128, 256 thr
    __shared__ float s[NNODE * TT];
    int bc = blockIdx.x, tid = threadIdx.x;
    const float* src = x + (size_t)bc * (NNODE * TT);
    for (int i = tid; i < NNODE * TT; i += 256) s[i] = src[i];
    __syncthreads();
    float* dst = g_Y0 + (size_t)bc * TT * NNODE;
    for (int i = tid; i < NNODE * TT; i += 256) {
        int t = i >> 9, n = i & 511;
        dst[i] = s[n * TT + t];
    }
}

// ---------------- copy A into g_B cols [0,512) ----------------
__global__ void k_copyA(const float* __restrict__ adj) {     // grid 64, 256 thr
    int base = blockIdx.x * 1024 + threadIdx.x;
#pragma unroll
    for (int q = 0; q < 4; q++) {
        int fidx = base + q * 256;                // quad index, 65536 total
        int row = fidx >> 7, c4 = (fidx & 127) * 4;
        *(float4*)&g_B[(size_t)row * 2048 + c4] =
            *(const float4*)&adj[(size_t)row * 512 + c4];
    }
}

// ---------------- 64(M) x 128(N) double-buffered SGEMM, K=512, f32x2 --------
__device__ __forceinline__ void sgemm(const float* __restrict__ A, int lda,
                                      const float* __restrict__ B, int ldb,
                                      float* __restrict__ C, int ldc,
                                      int m0, int n0) {
    __shared__ float As[2][16][64];
    __shared__ float Bs[2][16][128];
    int tid = threadIdx.x;
    int tx = tid & 15, ty = tid >> 4;              // n = tx*8, m = ty*4
    int ar = tid >> 2, ak = (tid & 3) << 2;        // A load: row, k
    const float* Ap = A + (size_t)(m0 + ar) * lda + ak;
    // B load: 512 quads, 2 per thread
    int bq0 = tid, bq1 = tid + 256;
    int bk0 = bq0 >> 5, bn0 = (bq0 & 31) << 2;
    int bk1 = bq1 >> 5, bn1 = (bq1 & 31) << 2;
    const float* Bp0 = B + (size_t)bk0 * ldb + n0 + bn0;
    const float* Bp1 = B + (size_t)bk1 * ldb + n0 + bn1;

    float4 av = *(const float4*)Ap;
    float4 bv0 = *(const float4*)Bp0;
    float4 bv1 = *(const float4*)Bp1;
    As[0][ak + 0][ar] = av.x; As[0][ak + 1][ar] = av.y;
    As[0][ak + 2][ar] = av.z; As[0][ak + 3][ar] = av.w;
    *(float4*)&Bs[0][bk0][bn0] = bv0;
    *(float4*)&Bs[0][bk1][bn1] = bv1;
    __syncthreads();

    unsigned long long acc[4][4];
#pragma unroll
    for (int i = 0; i < 4; i++)
#pragma unroll
        for (int j = 0; j < 4; j++) acc[i][j] = 0ull;

#pragma unroll 1
    for (int kt = 0; kt < 32; kt++) {
        int cur = kt & 1;
        if (kt < 31) {
            av  = *(const float4*)(Ap + (kt + 1) * 16);
            bv0 = *(const float4*)(Bp0 + (size_t)(kt + 1) * 16 * ldb);
            bv1 = *(const float4*)(Bp1 + (size_t)(kt + 1) * 16 * ldb);
        }
#pragma unroll
        for (int k = 0; k < 16; k++) {
            float4 a4 = *(const float4*)&As[cur][k][ty * 4];
            unsigned long long aa[4];
            aa[0] = pack2(a4.x, a4.x); aa[1] = pack2(a4.y, a4.y);
            aa[2] = pack2(a4.z, a4.z); aa[3] = pack2(a4.w, a4.w);
            longlong2 bA = *(const longlong2*)&Bs[cur][k][tx * 8];
            longlong2 bB = *(const longlong2*)&Bs[cur][k][tx * 8 + 4];
            unsigned long long b0 = (unsigned long long)bA.x;
            unsigned long long b1 = (unsigned long long)bA.y;
            unsigned long long b2 = (unsigned long long)bB.x;
            unsigned long long b3 = (unsigned long long)bB.y;
#pragma unroll
            for (int i = 0; i < 4; i++) {
                fma2(acc[i][0], aa[i], b0);
                fma2(acc[i][1], aa[i], b1);
                fma2(acc[i][2], aa[i], b2);
                fma2(acc[i][3], aa[i], b3);
            }
        }
        if (kt < 31) {
            int nx = cur ^ 1;
            As[nx][ak + 0][ar] = av.x; As[nx][ak + 1][ar] = av.y;
            As[nx][ak + 2][ar] = av.z; As[nx][ak + 3][ar] = av.w;
            *(float4*)&Bs[nx][bk0][bn0] = bv0;
            *(float4*)&Bs[nx][bk1][bn1] = bv1;
            __syncthreads();
        }
    }
#pragma unroll
    for (int i = 0; i < 4; i++) {
        F2U u0, u1, u2, u3;
        u0.u = acc[i][0]; u1.u = acc[i][1]; u2.u = acc[i][2]; u3.u = acc[i][3];
        float* cp = C + (size_t)(m0 + ty * 4 + i) * ldc + n0 + tx * 8;
        *(float4*)cp       = make_float4(u0.f.x, u0.f.y, u1.f.x, u1.f.y);
        *(float4*)(cp + 4) = make_float4(u2.f.x, u2.f.y, u3.f.x, u3.f.y);
    }
}

__global__ void __launch_bounds__(256, 3) k_pow2(const float* __restrict__ adj) {
    // A2 = A*A -> g_B cols [512,1024)   grid(4,8)
    sgemm(adj, 512, adj, 512, g_B + 512, 2048, blockIdx.y * 64, blockIdx.x * 128);
}
__global__ void __launch_bounds__(256, 3) k_pow34(const float* __restrict__ adj) {
    // z=0: A3 = A2*A -> cols [1024,1536);  z=1: A4 = A2*A2 -> cols [1536,2048)
    if (blockIdx.z == 0)
        sgemm(g_B + 512, 2048, adj, 512, g_B + 1024, 2048,
              blockIdx.y * 64, blockIdx.x * 128);
    else
        sgemm(g_B + 512, 2048, g_B + 512, 2048, g_B + 1536, 2048,
              blockIdx.y * 64, blockIdx.x * 128);
}
__global__ void __launch_bounds__(256, 3) k_hop() {
    // Yh = Y0(1536x512) * g_B(512x2048)   grid(16,24)
    sgemm(g_Y0, 512, g_B, 2048, g_Yh, 2048, blockIdx.y * 64, blockIdx.x * 128);
}

// ---------------- q_k = column sums of A^k (from g_B) ----------------
__global__ void k_qall() {                                   // grid 16, 128 thr
    int cg = blockIdx.x * 128 + threadIdx.x;                 // 0..2047
    float acc = 0.f;
#pragma unroll 8
    for (int v = 0; v < 512; v++) acc += g_B[(size_t)v * 2048 + cg];
    g_q[((cg >> 9) + 1) * NNODE + (cg & 511)] = acc;
}

// ---------------- fused composite chain (512 thr, dynamic smem) -------------
#define WS_STRIDE 132
#define SM_FLOATS (128 * WS_STRIDE + 6144 + 2 * 1280 + 2 * 640 + 1280 + 640)

__global__ void __launch_bounds__(512) k_composite(
    const float* __restrict__ W_start, const float* __restrict__ b_start,
    const float* __restrict__ W_skip,  const float* __restrict__ b_skip,
    const float* __restrict__ W_gc,    const float* __restrict__ b_gc,
    const float* __restrict__ gcg, const float* __restrict__ gcb,
    const float* __restrict__ gcm, const float* __restrict__ gcv,
    const float* __restrict__ bng, const float* __restrict__ bnb,
    const float* __restrict__ bnm, const float* __restrict__ bnv,
    const float* __restrict__ obg, const float* __restrict__ obb,
    const float* __restrict__ obm, const float* __restrict__ obv)
{
    extern __shared__ float sm[];
    float* Ws  = sm;                          // 128 * 132
    float* Sg  = Ws + 128 * WS_STRIDE;        // 6144
    float* CaA = Sg + 6144;                   // 1280
    float* CaB = CaA + 1280;                  // 1280
    float* UaA = CaB + 1280;                  // 640
    float* UaB = UaA + 640;                   // 640
    float* SkC = UaB + 640;                   // 1280
    float* SkU = SkC + 1280;                  // 640

    int tid = threadIdx.x;
    int c = tid >> 2, vq = tid & 3, v0 = vq * 4;

    for (int i2 = tid; i2 < 1280; i2 += 512) { CaA[i2] = 0.f; SkC[i2] = 0.f; }
    for (int i2 = tid; i2 < 640;  i2 += 512) { UaA[i2] = 0.f; SkU[i2] = 0.f; }
    __syncthreads();
    if (vq == 0) {
        CaA[c * 2 + 0] = W_start[c * 2 + 0];
        CaA[c * 2 + 1] = W_start[c * 2 + 1];
        UaA[c * 5] = b_start[c];
    }
    __syncthreads();

    float* Cac = CaA; float* Can = CaB;
    float* Uac = UaA; float* Uan = UaB;

    for (int s = 0; s < 5; s++) {
        int i = s >> 1;
        if ((s & 1) == 0) {
            // ---------- skip step i ----------
            for (int idx = tid; idx < 2048; idx += 512) {
                int m = idx >> 4, v = idx & 15; float val = 0.f;
                if (v < 10) val = Cac[(v >> 1) * 256 + m * 2 + (v & 1)];
                else if (v < 15) val = Uac[m * 5 + (v - 10)];
                Sg[idx] = val;
            }
            const float* Wp = W_skip + i * (DD * DD);
#pragma unroll
            for (int q = 0; q < 8; q++) {
                int fidx = q * 512 + tid;              // quad idx, 4096 total
                int cr = fidx >> 5, j4 = (fidx & 31) * 4;
                *(float4*)&Ws[cr * WS_STRIDE + j4] = *(const float4*)&Wp[cr * 128 + j4];
            }
            __syncthreads();
            float acc[4] = {0.f, 0.f, 0.f, 0.f};
            const float* wrow = Ws + c * WS_STRIDE;
            const float* sgv = Sg + v0;
#pragma unroll 4
            for (int m = 0; m < 128; m++) {
                float w = wrow[m];
                float4 sv = *(const float4*)&sgv[m * 16];
                acc[0] += w * sv.x; acc[1] += w * sv.y;
                acc[2] += w * sv.z; acc[3] += w * sv.w;
            }
#pragma unroll
            for (int u = 0; u < 4; u++) {
                int v = v0 + u;
                if (v < 10) SkC[(v >> 1) * 256 + c * 2 + (v & 1)] += acc[u];
                else if (v < 15)
                    SkU[c * 5 + (v - 10)] += acc[u] + ((v == 10) ? b_skip[i * DD + c] : 0.f);
            }
            __syncthreads();
        } else {
            // ---------- gc step i ----------
            for (int idx = tid; idx < 6144; idx += 512) {
                int j = idx >> 4, v = idx & 15;
                int sub = j >> 7, m = j & 127;
                float val = 0.f;
                if (v < 10) { int p = (v >> 1) - sub;
                              if (p >= 0) val = Cac[p * 256 + m * 2 + (v & 1)]; }
                else if (v < 15) { int kk = (v - 10) - sub;
                                   if (kk >= 0) val = Uac[m * 5 + kk]; }
                Sg[idx] = val;
            }
            float acc[4] = {0.f, 0.f, 0.f, 0.f};
            const float* Wg = W_gc + i * (DD * 3 * DD);
            for (int chunk = 0; chunk < 3; chunk++) {
#pragma unroll
                for (int q = 0; q < 8; q++) {
                    int fidx = q * 512 + tid;
                    int cr = fidx >> 5, j4 = (fidx & 31) * 4;
                    *(float4*)&Ws[cr * WS_STRIDE + j4] =
                        *(const float4*)&Wg[cr * 384 + chunk * 128 + j4];
                }
                __syncthreads();
                const float* wrow = Ws + c * WS_STRIDE;
                const float* sgv = Sg + (chunk * 128) * 16 + v0;
#pragma unroll 4
                for (int m = 0; m < 128; m++) {
                    float w = wrow[m];
                    float4 sv = *(const float4*)&sgv[m * 16];
                    acc[0] += w * sv.x; acc[1] += w * sv.y;
                    acc[2] += w * sv.z; acc[3] += w * sv.w;
                }
                __syncthreads();
            }
            float ig = gcg[i * DD + c] * rsqrtf(gcv[i * DD + c] + EPSBN);
            float mg = gcb[i * DD + c] - gcm[i * DD + c] * ig;
            float ib = bng[i * DD + c] * rsqrtf(bnv[i * DD + c] + EPSBN);
            float mb = bnb[i * DD + c] - bnm[i * DD + c] * ib;
#pragma unroll
            for (int u = 0; u < 4; u++) {
                int v = v0 + u;
                if (v < 10) {
                    int p = v >> 1, e = v & 1;
                    Can[p * 256 + c * 2 + e] =
                        ib * (ig * acc[u] + Cac[p * 256 + c * 2 + e]);
                } else if (v < 15) {
                    int kk = v - 10;
                    float h = acc[u] + ((kk == 0) ? b_gc[i * DD + c] : 0.f);
                    Uan[c * 5 + kk] = ib * (ig * h + ((kk == 0) ? mg : 0.f)
                                            + Uac[c * 5 + kk]) + ((kk == 0) ? mb : 0.f);
                }
            }
            __syncthreads();
            float* t1 = Cac; Cac = Can; Can = t1;
            float* t2 = Uac; Uac = Uan; Uan = t2;
        }
    }
    // finalize with output BN folded
    float io = obg[c] * rsqrtf(obv[c] + EPSBN);
    float mo = obb[c] - obm[c] * io;
#pragma unroll
    for (int u = 0; u < 4; u++) {
        int v = v0 + u;
        if (v < 10) g_Sfin[v * DD + c] = io * SkC[(v >> 1) * 256 + c * 2 + (v & 1)];
        else if (v < 15) g_SkUf[c * 5 + (v - 10)] = io * SkU[c * 5 + (v - 10)];
    }
    if (vq == 0) g_mo[c] = mo;
}

// ---------------- final expansion ----------------
__global__ void __launch_bounds__(256) k_final(float* __restrict__ out) {
    __shared__ float yv[10][32];
    __shared__ float S[10][128];
    __shared__ float qv[4][32];
    __shared__ float SkUs[DD * 5];
    __shared__ float mos[DD];
    int n0 = blockIdx.x * 32, t = blockIdx.y, b = blockIdx.z;
    int tid = threadIdx.x;
    for (int s = tid; s < 320; s += 256) {
        int j = s >> 5, ii = s & 31;
        int p = j >> 1, e = j & 1;
        int row = (b * 2 + e) * TT + t;
        yv[j][ii] = (p == 0)
            ? g_Y0[(size_t)row * NNODE + n0 + ii]
            : g_Yh[(size_t)row * 2048 + (p - 1) * 512 + n0 + ii];
    }
    for (int s = tid; s < 1280; s += 256) S[s >> 7][s & 127] = g_Sfin[s];
    for (int s = tid; s < 640; s += 256) SkUs[s] = g_SkUf[s];
    if (tid < 128) {
        qv[tid >> 5][tid & 31] = g_q[((tid >> 5) + 1) * NNODE + n0 + (tid & 31)];
        mos[tid] = g_mo[tid];
    }
    __syncthreads();
    int i = tid >> 3, c0 = (tid & 7) * 16;
    float q1 = qv[0][i], q2 = qv[1][i], q3 = qv[2][i], q4 = qv[3][i];
    float acc[16];
#pragma unroll
    for (int cc = 0; cc < 16; cc++) {
        int cch = c0 + cc;
        acc[cc] = mos[cch] + SkUs[cch * 5 + 0] + SkUs[cch * 5 + 1] * q1
                + SkUs[cch * 5 + 2] * q2 + SkUs[cch * 5 + 3] * q3
                + SkUs[cch * 5 + 4] * q4;
    }
#pragma unroll
    for (int j = 0; j < 10; j++) {
        float yj = yv[j][i];
#pragma unroll
        for (int cc = 0; cc < 16; cc++) acc[cc] += yj * S[j][c0 + cc];
    }
    float* op = out + (((size_t)(b * TT + t) * NNODE) + n0 + i) * DD + c0;
#pragma unroll
    for (int q4i = 0; q4i < 4; q4i++)
        *(float4*)(op + q4i * 4) = make_float4(acc[q4i * 4], acc[q4i * 4 + 1],
                                               acc[q4i * 4 + 2], acc[q4i * 4 + 3]);
}

// ---------------- launcher ----------------
extern "C" void kernel_launch(void* const* d_in, const int* in_sizes, int n_in,
                              void* d_out, int out_size) {
    const float* x       = (const float*)d_in[0];
    const float* adj     = (const float*)d_in[1];
    const float* W_start = (const float*)d_in[2];
    const float* b_start = (const float*)d_in[3];
    const float* W_skip  = (const float*)d_in[4];
    const float* b_skip  = (const float*)d_in[5];
    const float* W_gc    = (const float*)d_in[6];
    const float* b_gc    = (const float*)d_in[7];
    const float* gcg     = (const float*)d_in[8];
    const float* gcb     = (const float*)d_in[9];
    const float* gcm     = (const float*)d_in[10];
    const float* gcv     = (const float*)d_in[11];
    const float* bng     = (const float*)d_in[12];
    const float* bnb     = (const float*)d_in[13];
    const float* bnm     = (const float*)d_in[14];
    const float* bnv     = (const float*)d_in[15];
    const float* obg     = (const float*)d_in[16];
    const float* obb     = (const float*)d_in[17];
    const float* obm     = (const float*)d_in[18];
    const float* obv     = (const float*)d_in[19];
    float* out = (float*)d_out;

    static int smem_set = 0;
    if (!smem_set) {
        cudaFuncSetAttribute(k_composite, cudaFuncAttributeMaxDynamicSharedMemorySize,
                             SM_FLOATS * (int)sizeof(float));
        smem_set = 1;
    }

    k_transpose<<<128, 256>>>(x);
    k_copyA<<<64, 256>>>(adj);
    k_pow2<<<dim3(4, 8), 256>>>(adj);
    k_pow34<<<dim3(4, 8, 2), 256>>>(adj);
    k_hop<<<dim3(16, 24), 256>>>();
    k_qall<<<16, 128>>>();
    k_composite<<<1, 512, SM_FLOATS * sizeof(float)>>>(
        W_start, b_start, W_skip, b_skip, W_gc, b_gc,
        gcg, gcb, gcm, gcv, bng, bnb, bnm, bnv, obg, obb, obm, obv);
    k_final<<<dim3(16, 12, 64), 256>>>(out);
    (void)in_sizes; (void)n_in; (void)out_size;
}

// round 12
// speedup vs baseline: 1.1575x; 1.1575x over previous
#include <cuda_runtime.h>
#include <math.h>

#define NNODE 512
#define TT 12
#define DD 128
#define NROWS 1536            // 64*2*12 rows per Y plane
#define EPSBN 1e-5f

// ---------------- device scratch ----------------
__device__ float g_Y[5 * NROWS * NNODE];   // planes p=0..4, rows=(b*2+e)*12+t
__device__ float g_A2[NNODE * NNODE];
__device__ float g_q[5 * NNODE];           // rows 1..4 used
__device__ float g_Sfin[10 * DD];          // [j=p*2+e][c]
__device__ float g_SkUf[DD * 5];           // [c][k], ob-scaled
__device__ float g_mo[DD];

// ---------------- 64x64 double-buffered SGEMM core (K=N=512), R8-proven -----
__device__ __forceinline__ void sgemm64(const float* __restrict__ A,
                                        const float* __restrict__ B,
                                        float* __restrict__ C,
                                        int m0, int n0) {
    __shared__ float As[2][16][64];
    __shared__ float Bs[2][16][64];
    int tid = threadIdx.x;
    int tx = tid & 15, ty = tid >> 4;          // tx: n/4, ty: m/4
    int ar = tid >> 2, ak = (tid & 3) << 2;    // A tile load: row, k-col
    int bk = tid >> 4, bc = (tid & 15) << 2;   // B tile load: k-row, col
    const float* Ap = A + (size_t)(m0 + ar) * 512 + ak;
    const float* Bp = B + (size_t)bk * 512 + n0 + bc;

    float4 av = *(const float4*)Ap;
    float4 bv = *(const float4*)Bp;
    As[0][ak + 0][ar] = av.x; As[0][ak + 1][ar] = av.y;
    As[0][ak + 2][ar] = av.z; As[0][ak + 3][ar] = av.w;
    *(float4*)&Bs[0][bk][bc] = bv;
    __syncthreads();

    float acc[4][4] = {};
#pragma unroll 1
    for (int kt = 0; kt < 32; kt++) {
        int cur = kt & 1;
        if (kt < 31) {
            av = *(const float4*)(Ap + (kt + 1) * 16);
            bv = *(const float4*)(Bp + (size_t)(kt + 1) * 16 * 512);
        }
#pragma unroll
        for (int k = 0; k < 16; k++) {
            float a[4], b[4];
            *(float4*)a = *(const float4*)&As[cur][k][ty * 4];
            *(float4*)b = *(const float4*)&Bs[cur][k][tx * 4];
#pragma unroll
            for (int i = 0; i < 4; i++)
#pragma unroll
                for (int j = 0; j < 4; j++) acc[i][j] += a[i] * b[j];
        }
        if (kt < 31) {
            int nx = cur ^ 1;
            As[nx][ak + 0][ar] = av.x; As[nx][ak + 1][ar] = av.y;
            As[nx][ak + 2][ar] = av.z; As[nx][ak + 3][ar] = av.w;
            *(float4*)&Bs[nx][bk][bc] = bv;
            __syncthreads();
        }
    }
#pragma unroll
    for (int i = 0; i < 4; i++) {
        float4 v = make_float4(acc[i][0], acc[i][1], acc[i][2], acc[i][3]);
        *(float4*)(C + (size_t)(m0 + ty * 4 + i) * 512 + n0 + tx * 4) = v;
    }
}

// ---------------- composite chain (1 block, 256 thr, chunked coalesced W) ---
__device__ void composite_run(float* sm,
    const float* __restrict__ W_start, const float* __restrict__ b_start,
    const float* __restrict__ W_skip,  const float* __restrict__ b_skip,
    const float* __restrict__ W_gc,    const float* __restrict__ b_gc,
    const float* __restrict__ gcg, const float* __restrict__ gcb,
    const float* __restrict__ gcm, const float* __restrict__ gcv,
    const float* __restrict__ bng, const float* __restrict__ bnb,
    const float* __restrict__ bnm, const float* __restrict__ bnv,
    const float* __restrict__ obg, const float* __restrict__ obb,
    const float* __restrict__ obm, const float* __restrict__ obv)
{
    float* Ws  = sm;                 // 128*68 = 8704
    float* Sg  = Ws + 8704;          // 6144
    float* CaA = Sg + 6144;          // 1280
    float* CaB = CaA + 1280;         // 1280
    float* UaA = CaB + 1280;         // 640
    float* UaB = UaA + 640;          // 640
    float* SkC = UaB + 640;          // 1280
    float* SkU = SkC + 1280;         // 640   total 20608 floats
    int tid = threadIdx.x;
    int c = tid >> 1, vq = tid & 1, v0 = vq * 8;

    for (int i2 = tid; i2 < 1280; i2 += 256) { CaA[i2] = 0.f; SkC[i2] = 0.f; }
    for (int i2 = tid; i2 < 640;  i2 += 256) { UaA[i2] = 0.f; SkU[i2] = 0.f; }
    __syncthreads();
    if (vq == 0) {
        CaA[c * 2 + 0] = W_start[c * 2 + 0];
        CaA[c * 2 + 1] = W_start[c * 2 + 1];
        UaA[c * 5] = b_start[c];
    }
    __syncthreads();

    float *Cac = CaA, *Can = CaB, *Uac = UaA, *Uan = UaB;

    for (int s = 0; s < 5; s++) {
        int i = s >> 1;
        int isgc = s & 1;
        // ---- stage composite vectors into Sg[j][16] ----
        if (!isgc) {
            for (int idx = tid; idx < 2048; idx += 256) {
                int m = idx >> 4, v = idx & 15; float val = 0.f;
                if (v < 10) val = Cac[(v >> 1) * 256 + m * 2 + (v & 1)];
                else if (v < 15) val = Uac[m * 5 + (v - 10)];
                Sg[idx] = val;
            }
        } else {
            for (int idx = tid; idx < 6144; idx += 256) {
                int j = idx >> 4, v = idx & 15;
                int sub = j >> 7, m = j & 127;
                float val = 0.f;
                if (v < 10) { int p = (v >> 1) - sub;
                              if (p >= 0) val = Cac[p * 256 + m * 2 + (v & 1)]; }
                else if (v < 15) { int kk = (v - 10) - sub;
                                   if (kk >= 0) val = Uac[m * 5 + kk]; }
                Sg[idx] = val;
            }
        }
        const float* Wbase = isgc ? (W_gc + i * (DD * 3 * DD)) : (W_skip + i * (DD * DD));
        int wld = isgc ? 384 : 128;
        int nch = isgc ? 6 : 2;
        float acc[8];
#pragma unroll
        for (int u = 0; u < 8; u++) acc[u] = 0.f;

        for (int ch = 0; ch < nch; ch++) {
            int j0 = ch * 64;
            __syncthreads();                       // Sg visible / Ws reusable
#pragma unroll
            for (int q = 0; q < 8; q++) {          // stage 128x64 W chunk, coalesced
                int fidx = q * 256 + tid;
                int r = fidx >> 4, col4 = (fidx & 15) * 4;
                *(float4*)&Ws[r * 68 + col4] = *(const float4*)&Wbase[r * wld + j0 + col4];
            }
            __syncthreads();
            const float* wrow = Ws + c * 68;
#pragma unroll 4
            for (int m = 0; m < 64; m++) {
                float w = wrow[m];
                const float* sgp = Sg + (j0 + m) * 16 + v0;
                float4 a = *(const float4*)sgp;
                float4 b = *(const float4*)(sgp + 4);
                acc[0] += w * a.x; acc[1] += w * a.y; acc[2] += w * a.z; acc[3] += w * a.w;
                acc[4] += w * b.x; acc[5] += w * b.y; acc[6] += w * b.z; acc[7] += w * b.w;
            }
        }
        __syncthreads();
        if (!isgc) {
#pragma unroll
            for (int u = 0; u < 8; u++) {
                int v = v0 + u;
                if (v < 10) SkC[(v >> 1) * 256 + c * 2 + (v & 1)] += acc[u];
                else if (v < 15)
                    SkU[c * 5 + (v - 10)] += acc[u] + ((v == 10) ? b_skip[i * DD + c] : 0.f);
            }
        } else {
            float ig = gcg[i * DD + c] * rsqrtf(gcv[i * DD + c] + EPSBN);
            float mg = gcb[i * DD + c] - gcm[i * DD + c] * ig;
            float ib = bng[i * DD + c] * rsqrtf(bnv[i * DD + c] + EPSBN);
            float mb = bnb[i * DD + c] - bnm[i * DD + c] * ib;
#pragma unroll
            for (int u = 0; u < 8; u++) {
                int v = v0 + u;
                if (v < 10) {
                    int p = v >> 1, e = v & 1;
                    Can[p * 256 + c * 2 + e] = ib * (ig * acc[u] + Cac[p * 256 + c * 2 + e]);
                } else if (v < 15) {
                    int kk = v - 10;
                    float h = acc[u] + ((kk == 0) ? b_gc[i * DD + c] : 0.f);
                    Uan[c * 5 + kk] = ib * (ig * h + ((kk == 0) ? mg : 0.f)
                                            + Uac[c * 5 + kk]) + ((kk == 0) ? mb : 0.f);
                }
            }
            float* t;
            t = Cac; Cac = Can; Can = t;
            t = Uac; Uac = Uan; Uan = t;
        }
        __syncthreads();
    }
    // finalize with output BN folded
    float io = obg[c] * rsqrtf(obv[c] + EPSBN);
    float mo = obb[c] - obm[c] * io;
#pragma unroll
    for (int u = 0; u < 8; u++) {
        int v = v0 + u;
        if (v < 10) g_Sfin[v * DD + c] = io * SkC[(v >> 1) * 256 + c * 2 + (v & 1)];
        else if (v < 15) g_SkUf[c * 5 + (v - 10)] = io * SkU[c * 5 + (v - 10)];
    }
    if (vq == 0) g_mo[c] = mo;
}

#define COMP_SMEM_BYTES (20608 * 4)

// ---------------- K1: transpose || A2 || q1 || composite ----------------
__global__ void __launch_bounds__(256) k_stage1(
    const float* __restrict__ x, const float* __restrict__ adj,
    const float* __restrict__ W_start, const float* __restrict__ b_start,
    const float* __restrict__ W_skip,  const float* __restrict__ b_skip,
    const float* __restrict__ W_gc,    const float* __restrict__ b_gc,
    const float* __restrict__ gcg, const float* __restrict__ gcb,
    const float* __restrict__ gcm, const float* __restrict__ gcv,
    const float* __restrict__ bng, const float* __restrict__ bnb,
    const float* __restrict__ bnm, const float* __restrict__ bnv,
    const float* __restrict__ obg, const float* __restrict__ obb,
    const float* __restrict__ obm, const float* __restrict__ obv)
{
    extern __shared__ float sm[];
    int bid = blockIdx.x, tid = threadIdx.x;
    if (bid < 128) {
        // transpose x[b,e][n][t] -> Y0[b,e][t][n]
        const float* src = x + (size_t)bid * (NNODE * TT);
        for (int i = tid; i < NNODE * TT; i += 256) sm[i] = src[i];
        __syncthreads();
        float* dst = g_Y + (size_t)bid * TT * NNODE;
        for (int i = tid; i < NNODE * TT; i += 256) {
            int t = i >> 9, n = i & 511;
            dst[i] = sm[n * TT + t];
        }
    } else if (bid < 192) {
        int t = bid - 128;
        sgemm64(adj, adj, g_A2, (t >> 3) * 64, (t & 7) * 64);
    } else if (bid < 200) {
        int bq = bid - 192;
        int col = bq * 64 + (tid & 63);
        int rs = tid >> 6;
        float a = 0.f;
#pragma unroll 8
        for (int v = rs * 128; v < rs * 128 + 128; v++) a += adj[(size_t)v * 512 + col];
        sm[tid] = a;
        __syncthreads();
        if (rs == 0)
            g_q[512 + col] = sm[tid] + sm[tid + 64] + sm[tid + 128] + sm[tid + 192];
    } else {
        composite_run(sm, W_start, b_start, W_skip, b_skip, W_gc, b_gc,
                      gcg, gcb, gcm, gcv, bng, bnb, bnm, bnv, obg, obb, obm, obv);
    }
}

// ---------------- K2: Y1 = Y0*A || q2 = colsum(A2) ----------------
__global__ void __launch_bounds__(256) k_stage2(const float* __restrict__ adj) {
    int bid = blockIdx.x, tid = threadIdx.x;
    if (bid < 192) {
        sgemm64(g_Y, adj, g_Y + (size_t)1 * NROWS * NNODE,
                (bid >> 3) * 64, (bid & 7) * 64);
    } else {
        __shared__ float red[256];
        int bq = bid - 192;
        int col = bq * 64 + (tid & 63);
        int rs = tid >> 6;
        float a = 0.f;
#pragma unroll 8
        for (int v = rs * 128; v < rs * 128 + 128; v++) a += g_A2[(size_t)v * 512 + col];
        red[tid] = a;
        __syncthreads();
        if (rs == 0)
            g_q[1024 + col] = red[tid] + red[tid + 64] + red[tid + 128] + red[tid + 192];
    }
}

// ---------------- K3: Y2 = Y1*A || Y3 = Y1*A2 || q3,q4 ----------------
__global__ void __launch_bounds__(256) k_stage3(const float* __restrict__ adj) {
    int bid = blockIdx.x, tid = threadIdx.x;
    if (bid < 192) {
        sgemm64(g_Y + (size_t)1 * NROWS * NNODE, adj,
                g_Y + (size_t)2 * NROWS * NNODE, (bid >> 3) * 64, (bid & 7) * 64);
    } else if (bid < 384) {
        int t = bid - 192;
        sgemm64(g_Y + (size_t)1 * NROWS * NNODE, g_A2,
                g_Y + (size_t)3 * NROWS * NNODE, (t >> 3) * 64, (t & 7) * 64);
    } else {
        __shared__ float qs[512];
        int src = (bid == 384) ? 1 : 2;
        for (int i = tid; i < 512; i += 256) qs[i] = g_q[src * 512 + i];
        __syncthreads();
        for (int w = tid; w < 512; w += 256) {
            float a = 0.f;
#pragma unroll 8
            for (int v = 0; v < 512; v++) a += qs[v] * g_A2[(size_t)v * 512 + w];
            g_q[(src + 2) * 512 + w] = a;
        }
    }
}

// ---------------- K4: Y4 = Y2*A2 ----------------
__global__ void __launch_bounds__(256) k_stage4() {
    int bid = blockIdx.x;
    sgemm64(g_Y + (size_t)2 * NROWS * NNODE, g_A2,
            g_Y + (size_t)4 * NROWS * NNODE, (bid >> 3) * 64, (bid & 7) * 64);
}

// ---------------- K5: final expansion ----------------
__global__ void __launch_bounds__(256) k_final(float* __restrict__ out) {
    __shared__ float yv[10][32];
    __shared__ float S[10][128];
    __shared__ float qv[4][32];
    __shared__ float SkUs[DD * 5];
    __shared__ float mos[DD];
    int n0 = blockIdx.x * 32, t = blockIdx.y, b = blockIdx.z;
    int tid = threadIdx.x;
    for (int s = tid; s < 320; s += 256) {
        int j = s >> 5, ii = s & 31;
        int p = j >> 1, e = j & 1;
        yv[j][ii] = g_Y[((size_t)p * NROWS + (b * 2 + e) * TT + t) * NNODE + n0 + ii];
    }
    for (int s = tid; s < 1280; s += 256) S[s >> 7][s & 127] = g_Sfin[s];
    for (int s = tid; s < 640; s += 256) SkUs[s] = g_SkUf[s];
    if (tid < 128) {
        qv[tid >> 5][tid & 31] = g_q[((tid >> 5) + 1) * NNODE + n0 + (tid & 31)];
        mos[tid] = g_mo[tid];
    }
    __syncthreads();
    int i = tid >> 3, c0 = (tid & 7) * 16;
    float q1 = qv[0][i], q2 = qv[1][i], q3 = qv[2][i], q4 = qv[3][i];
    float acc[16];
#pragma unroll
    for (int cc = 0; cc < 16; cc++) {
        int cch = c0 + cc;
        acc[cc] = mos[cch] + SkUs[cch * 5 + 0] + SkUs[cch * 5 + 1] * q1
                + SkUs[cch * 5 + 2] * q2 + SkUs[cch * 5 + 3] * q3
                + SkUs[cch * 5 + 4] * q4;
    }
#pragma unroll
    for (int j = 0; j < 10; j++) {
        float yj = yv[j][i];
#pragma unroll
        for (int cc = 0; cc < 16; cc++) acc[cc] += yj * S[j][c0 + cc];
    }
    float* op = out + (((size_t)(b * TT + t) * NNODE) + n0 + i) * DD + c0;
#pragma unroll
    for (int q4i = 0; q4i < 4; q4i++)
        *(float4*)(op + q4i * 4) = make_float4(acc[q4i * 4], acc[q4i * 4 + 1],
                                               acc[q4i * 4 + 2], acc[q4i * 4 + 3]);
}

// ---------------- launcher ----------------
extern "C" void kernel_launch(void* const* d_in, const int* in_sizes, int n_in,
                              void* d_out, int out_size) {
    const float* x       = (const float*)d_in[0];
    const float* adj     = (const float*)d_in[1];
    const float* W_start = (const float*)d_in[2];
    const float* b_start = (const float*)d_in[3];
    const float* W_skip  = (const float*)d_in[4];
    const float* b_skip  = (const float*)d_in[5];
    const float* W_gc    = (const float*)d_in[6];
    const float* b_gc    = (const float*)d_in[7];
    const float* gcg     = (const float*)d_in[8];
    const float* gcb     = (const float*)d_in[9];
    const float* gcm     = (const float*)d_in[10];
    const float* gcv     = (const float*)d_in[11];
    const float* bng     = (const float*)d_in[12];
    const float* bnb     = (const float*)d_in[13];
    const float* bnm     = (const float*)d_in[14];
    const float* bnv     = (const float*)d_in[15];
    const float* obg     = (const float*)d_in[16];
    const float* obb     = (const float*)d_in[17];
    const float* obm     = (const float*)d_in[18];
    const float* obv     = (const float*)d_in[19];
    float* out = (float*)d_out;

    static int smem_set = 0;
    if (!smem_set) {
        cudaFuncSetAttribute(k_stage1, cudaFuncAttributeMaxDynamicSharedMemorySize,
                             COMP_SMEM_BYTES);
        smem_set = 1;
    }

    k_stage1<<<201, 256, COMP_SMEM_BYTES>>>(x, adj, W_start, b_start, W_skip, b_skip,
                                            W_gc, b_gc, gcg, gcb, gcm, gcv,
                                            bng, bnb, bnm, bnv, obg, obb, obm, obv);
    k_stage2<<<200, 256>>>(adj);
    k_stage3<<<386, 256>>>(adj);
    k_stage4<<<192, 256>>>();
    k_final<<<dim3(16, 12, 64), 256>>>(out);
    (void)in_sizes; (void)n_in; (void)out_size;
}

// round 13
// speedup vs baseline: 1.2385x; 1.0700x over previous
#include <cuda_runtime.h>
#include <math.h>

#define GRID 444
#define TT 12
#define DD 128
#define NPL (1536 * 512)          // floats per Y plane
#define EPSBN 1e-5f

// ---------------- device scratch ----------------
__device__ float g_Y[5 * NPL];            // planes p=0..4, rows=(b*2+e)*12+t
__device__ float g_A2a[512 * 512];        // A^2 split-K part (k<256)
__device__ float g_A2b[512 * 512];        // A^2 split-K part (k>=256)
__device__ float g_q[5 * 512];            // q_k = 1^T A^k, rows 1..4
__device__ float g_Sfin[10 * DD];
__device__ float g_SkUf[DD * 5];
__device__ float g_mo[DD];
__device__ unsigned g_bcnt = 0u;
__device__ unsigned g_bgen = 0u;

// ---------------- grid-wide barrier (all 444 blocks resident) ----------------
__device__ __forceinline__ void grid_sync() {
    __threadfence();
    __syncthreads();
    if (threadIdx.x == 0) {
        unsigned gen = atomicAdd(&g_bgen, 0u);
        if (atomicAdd(&g_bcnt, 1u) == (unsigned)GRID - 1u) {
            atomicExch(&g_bcnt, 0u);
            __threadfence();
            atomicAdd(&g_bgen, 1u);
        } else {
            while (atomicAdd(&g_bgen, 0u) == gen) __nanosleep(128);
        }
        __threadfence();
    }
    __syncthreads();
}

// ---------------- 64x64 double-buffered SGEMM tile (optional summed operands)
__device__ __forceinline__ void sgemm64(float* SM,
        const float* __restrict__ A, const float* __restrict__ Ab,
        const float* __restrict__ B, const float* __restrict__ Bb,
        float* __restrict__ C, int m0, int n0, int k0, int nk)
{
    float (*As)[16][64] = (float(*)[16][64])SM;
    float (*Bs)[16][64] = (float(*)[16][64])(SM + 2048);
    int tid = threadIdx.x;
    int tx = tid & 15, ty = tid >> 4;
    int ar = tid >> 2, ak = (tid & 3) << 2;
    int bk = tid >> 4, bc = (tid & 15) << 2;
    const float* Ap = A + (size_t)(m0 + ar) * 512 + k0 + ak;
    const float* Bp = B + (size_t)(k0 + bk) * 512 + n0 + bc;
    ptrdiff_t dA = Ab ? (Ab - A) : 0;
    ptrdiff_t dB = Bb ? (Bb - B) : 0;

    float4 av = *(const float4*)Ap;
    if (Ab) { float4 e = *(const float4*)(Ap + dA);
              av.x += e.x; av.y += e.y; av.z += e.z; av.w += e.w; }
    float4 bv = *(const float4*)Bp;
    if (Bb) { float4 e = *(const float4*)(Bp + dB);
              bv.x += e.x; bv.y += e.y; bv.z += e.z; bv.w += e.w; }
    As[0][ak + 0][ar] = av.x; As[0][ak + 1][ar] = av.y;
    As[0][ak + 2][ar] = av.z; As[0][ak + 3][ar] = av.w;
    *(float4*)&Bs[0][bk][bc] = bv;
    __syncthreads();

    float acc[4][4] = {};
#pragma unroll 1
    for (int kt = 0; kt < nk; kt++) {
        int cur = kt & 1;
        if (kt < nk - 1) {
            av = *(const float4*)(Ap + (kt + 1) * 16);
            if (Ab) { float4 e = *(const float4*)(Ap + (kt + 1) * 16 + dA);
                      av.x += e.x; av.y += e.y; av.z += e.z; av.w += e.w; }
            bv = *(const float4*)(Bp + (size_t)(kt + 1) * 16 * 512);
            if (Bb) { float4 e = *(const float4*)(Bp + (size_t)(kt + 1) * 16 * 512 + dB);
                      bv.x += e.x; bv.y += e.y; bv.z += e.z; bv.w += e.w; }
        }
#pragma unroll
        for (int k = 0; k < 16; k++) {
            float a[4], b[4];
            *(float4*)a = *(const float4*)&As[cur][k][ty * 4];
            *(float4*)b = *(const float4*)&Bs[cur][k][tx * 4];
#pragma unroll
            for (int i = 0; i < 4; i++)
#pragma unroll
                for (int j = 0; j < 4; j++) acc[i][j] += a[i] * b[j];
        }
        if (kt < nk - 1) {
            int nx = cur ^ 1;
            As[nx][ak + 0][ar] = av.x; As[nx][ak + 1][ar] = av.y;
            As[nx][ak + 2][ar] = av.z; As[nx][ak + 3][ar] = av.w;
            *(float4*)&Bs[nx][bk][bc] = bv;
            __syncthreads();
        }
    }
#pragma unroll
    for (int i = 0; i < 4; i++) {
        float4 v = make_float4(acc[i][0], acc[i][1], acc[i][2], acc[i][3]);
        *(float4*)(C + (size_t)(m0 + ty * 4 + i) * 512 + n0 + tx * 4) = v;
    }
}

// ---------------- column-sum / q^T M tasks (64 cols per task) ----------------
__device__ void colsum_task(float* SM, const float* __restrict__ M,
                            const float* __restrict__ M2, float* dst, int blk) {
    int tid = threadIdx.x;
    int col = blk * 64 + (tid & 63);
    int rs = tid >> 6;
    float a = 0.f;
#pragma unroll 8
    for (int v = rs * 128; v < rs * 128 + 128; v++) {
        a += M[(size_t)v * 512 + col];
        if (M2) a += M2[(size_t)v * 512 + col];
    }
    SM[512 + tid] = a;
    __syncthreads();
    if (rs == 0)
        dst[col] = SM[512 + tid] + SM[512 + tid + 64]
                 + SM[512 + tid + 128] + SM[512 + tid + 192];
}

__device__ void vecmat_task(float* SM, const float* __restrict__ qsrc,
                            const float* __restrict__ M, const float* __restrict__ M2,
                            float* dst, int blk) {
    int tid = threadIdx.x;
    for (int i = tid; i < 512; i += 256) SM[i] = qsrc[i];
    __syncthreads();
    int col = blk * 64 + (tid & 63);
    int rs = tid >> 6;
    float a = 0.f;
#pragma unroll 8
    for (int v = rs * 128; v < rs * 128 + 128; v++)
        a += SM[v] * (M[(size_t)v * 512 + col] + M2[(size_t)v * 512 + col]);
    SM[512 + tid] = a;
    __syncthreads();
    if (rs == 0)
        dst[col] = SM[512 + tid] + SM[512 + tid + 64]
                 + SM[512 + tid + 128] + SM[512 + tid + 192];
}

// ---------------- warp-cooperative composite chain (1 block) ----------------
__device__ void composite_run(float* SM,
    const float* __restrict__ W_start, const float* __restrict__ b_start,
    const float* __restrict__ W_skip,  const float* __restrict__ b_skip,
    const float* __restrict__ W_gc,    const float* __restrict__ b_gc,
    const float* __restrict__ gcg, const float* __restrict__ gcb,
    const float* __restrict__ gcm, const float* __restrict__ gcv,
    const float* __restrict__ bng, const float* __restrict__ bnb,
    const float* __restrict__ bnm, const float* __restrict__ bnv,
    const float* __restrict__ obg, const float* __restrict__ obb,
    const float* __restrict__ obm, const float* __restrict__ obv)
{
    float* Sg  = SM;              // 384*15 = 5760
    float* Ca  = SM + 5760;       // 1280  [p*256 + c*2 + e]
    float* Ua  = Ca + 1280;       // 640   [c*5 + k]
    float* SkC = Ua + 640;        // 1280
    float* SkU = SkC + 1280;      // 640
    int tid = threadIdx.x, wid = tid >> 5, lane = tid & 31;

    for (int i = tid; i < 1280; i += 256) { Ca[i] = 0.f; SkC[i] = 0.f; }
    for (int i = tid; i < 640;  i += 256) { Ua[i] = 0.f; SkU[i] = 0.f; }
    __syncthreads();
    if (tid < 128) {
        Ca[tid * 2 + 0] = W_start[tid * 2 + 0];
        Ca[tid * 2 + 1] = W_start[tid * 2 + 1];
        Ua[tid * 5] = b_start[tid];
    }
    __syncthreads();

    for (int s = 0; s < 5; s++) {
        int i = s >> 1;
        int isgc = s & 1;
        int jmax = isgc ? 384 : 128;
        for (int j = tid; j < jmax; j += 256) {
            int sub = j >> 7, m = j & 127;
#pragma unroll
            for (int v = 0; v < 10; v++) {
                int p = (v >> 1) - sub;
                Sg[j * 15 + v] = (p >= 0) ? Ca[p * 256 + m * 2 + (v & 1)] : 0.f;
            }
#pragma unroll
            for (int k = 0; k < 5; k++) {
                int kk = k - sub;
                Sg[j * 15 + 10 + k] = (kk >= 0) ? Ua[m * 5 + kk] : 0.f;
            }
        }
        __syncthreads();
        const float* Wb = isgc ? (W_gc + i * 128 * 384) : (W_skip + i * 128 * 128);
        for (int ci = 0; ci < 16; ci++) {
            int c = wid * 16 + ci;
            const float* Wr = Wb + (size_t)c * jmax;
            float acc[15];
#pragma unroll
            for (int v = 0; v < 15; v++) acc[v] = 0.f;
            if (isgc) {
                float w[12];
#pragma unroll
                for (int u = 0; u < 12; u++) w[u] = Wr[lane + u * 32];
#pragma unroll
                for (int u = 0; u < 12; u++) {
                    const float* sp = &Sg[(lane + u * 32) * 15];
#pragma unroll
                    for (int v = 0; v < 15; v++) acc[v] += w[u] * sp[v];
                }
            } else {
                float w[4];
#pragma unroll
                for (int u = 0; u < 4; u++) w[u] = Wr[lane + u * 32];
#pragma unroll
                for (int u = 0; u < 4; u++) {
                    const float* sp = &Sg[(lane + u * 32) * 15];
#pragma unroll
                    for (int v = 0; v < 15; v++) acc[v] += w[u] * sp[v];
                }
            }
            float mine = 0.f;
#pragma unroll
            for (int v = 0; v < 15; v++) {
                float r = acc[v];
#pragma unroll
                for (int o = 16; o; o >>= 1) r += __shfl_xor_sync(0xffffffffu, r, o);
                if (lane == v) mine = r;
            }
            if (!isgc) {
                if (lane < 10) {
                    SkC[(lane >> 1) * 256 + c * 2 + (lane & 1)] += mine;
                } else if (lane < 15) {
                    int kk = lane - 10;
                    SkU[c * 5 + kk] += mine + ((kk == 0) ? b_skip[i * 128 + c] : 0.f);
                }
            } else if (lane < 15) {
                float ig = gcg[i * 128 + c] * rsqrtf(gcv[i * 128 + c] + EPSBN);
                float mg = gcb[i * 128 + c] - gcm[i * 128 + c] * ig;
                float ib = bng[i * 128 + c] * rsqrtf(bnv[i * 128 + c] + EPSBN);
                float mb = bnb[i * 128 + c] - bnm[i * 128 + c] * ib;
                if (lane < 10) {
                    int p = lane >> 1, e = lane & 1, id = p * 256 + c * 2 + e;
                    Ca[id] = ib * (ig * mine + Ca[id]);
                } else {
                    int kk = lane - 10, id = c * 5 + kk;
                    float h = mine + ((kk == 0) ? b_gc[i * 128 + c] : 0.f);
                    Ua[id] = ib * (ig * h + ((kk == 0) ? mg : 0.f) + Ua[id])
                           + ((kk == 0) ? mb : 0.f);
                }
            }
        }
        __syncthreads();
    }
    if (tid < 128) {
        int c = tid;
        float io = obg[c] * rsqrtf(obv[c] + EPSBN);
        float mo = obb[c] - obm[c] * io;
#pragma unroll
        for (int v = 0; v < 10; v++)
            g_Sfin[v * 128 + c] = io * SkC[(v >> 1) * 256 + c * 2 + (v & 1)];
#pragma unroll
        for (int k = 0; k < 5; k++) g_SkUf[c * 5 + k] = io * SkU[c * 5 + k];
        g_mo[c] = mo;
    }
}

// ---------------- the single persistent kernel ----------------
__global__ void __launch_bounds__(256, 3) k_mega(
    const float* __restrict__ x, const float* __restrict__ adj,
    const float* __restrict__ W_start, const float* __restrict__ b_start,
    const float* __restrict__ W_skip,  const float* __restrict__ b_skip,
    const float* __restrict__ W_gc,    const float* __restrict__ b_gc,
    const float* __restrict__ gcg, const float* __restrict__ gcb,
    const float* __restrict__ gcm, const float* __restrict__ gcv,
    const float* __restrict__ bng, const float* __restrict__ bnb,
    const float* __restrict__ bnm, const float* __restrict__ bnv,
    const float* __restrict__ obg, const float* __restrict__ obb,
    const float* __restrict__ obm, const float* __restrict__ obv,
    float* __restrict__ out)
{
    __shared__ float SM[9600];           // 38.4 KB, union for all phases
    int bid = blockIdx.x, tid = threadIdx.x;

    // ======== P0: transpose(128) | A2 split-K(128) | q1(8) ========
    for (int t = bid; t < 264; t += GRID) {
        __syncthreads();
        if (t < 128) {
            const float* src = x + (size_t)t * 6144;
            for (int i = tid; i < 6144; i += 256) SM[i] = src[i];
            __syncthreads();
            float* dst = g_Y + (size_t)t * 6144;
            for (int i = tid; i < 6144; i += 256) {
                int tt = i >> 9, n = i & 511;
                dst[i] = SM[n * TT + tt];
            }
        } else if (t < 256) {
            int s = (t - 128) >> 6, tile = (t - 128) & 63;
            sgemm64(SM, adj, nullptr, adj, nullptr, s ? g_A2b : g_A2a,
                    (tile >> 3) * 64, (tile & 7) * 64, s * 256, 16);
        } else {
            colsum_task(SM, adj, nullptr, g_q + 512, t - 256);
        }
    }
    grid_sync();

    // ======== P1: Y1(192) | Y2(192) | q2(8) | q3(8) | composite(1) ========
    for (int t = bid; t < 401; t += GRID) {
        __syncthreads();
        if (t < 192) {
            sgemm64(SM, g_Y, nullptr, adj, nullptr, g_Y + NPL,
                    (t >> 3) * 64, (t & 7) * 64, 0, 32);
        } else if (t < 384) {
            int u = t - 192;
            sgemm64(SM, g_Y, nullptr, g_A2a, g_A2b, g_Y + 2 * NPL,
                    (u >> 3) * 64, (u & 7) * 64, 0, 32);
        } else if (t < 392) {
            colsum_task(SM, g_A2a, g_A2b, g_q + 1024, t - 384);
        } else if (t < 400) {
            vecmat_task(SM, g_q + 512, g_A2a, g_A2b, g_q + 1536, t - 392);
        } else {
            composite_run(SM, W_start, b_start, W_skip, b_skip, W_gc, b_gc,
                          gcg, gcb, gcm, gcv, bng, bnb, bnm, bnv,
                          obg, obb, obm, obv);
        }
    }
    grid_sync();

    // ======== P2: Y3=Y1*A2(192) | Y4=Y2*A2(192) | q4(8) ========
    for (int t = bid; t < 392; t += GRID) {
        __syncthreads();
        if (t < 192) {
            sgemm64(SM, g_Y + NPL, nullptr, g_A2a, g_A2b, g_Y + 3 * NPL,
                    (t >> 3) * 64, (t & 7) * 64, 0, 32);
        } else if (t < 384) {
            int u = t - 192;
            sgemm64(SM, g_Y + 2 * NPL, nullptr, g_A2a, g_A2b, g_Y + 4 * NPL,
                    (u >> 3) * 64, (u & 7) * 64, 0, 32);
        } else {
            vecmat_task(SM, g_q + 1024, g_A2a, g_A2b, g_q + 2048, t - 384);
        }
    }
    grid_sync();

    // ======== P3: final expansion (12288 tiles of 32 nodes) ========
    {
        float* S    = SM;            // 1280
        float* SkUs = SM + 1280;     // 640
        float* mos  = SM + 1920;     // 128
        float* qs   = SM + 2048;     // 2048
        for (int i = tid; i < 1280; i += 256) S[i] = g_Sfin[i];
        for (int i = tid; i < 640;  i += 256) SkUs[i] = g_SkUf[i];
        if (tid < 128) mos[tid] = g_mo[tid];
        for (int i = tid; i < 2048; i += 256) qs[i] = g_q[512 + i];
        __syncthreads();
        int i = tid >> 3, c0 = (tid & 7) * 16;
        for (int task = bid; task < 12288; task += GRID) {
            int nt = task & 15, bt = task >> 4;
            int b = bt / TT, tt = bt - b * TT;
            int n = nt * 32 + i;
            float y[10];
#pragma unroll
            for (int j = 0; j < 10; j++) {
                int p = j >> 1, e = j & 1;
                y[j] = g_Y[(size_t)p * NPL + (size_t)((b * 2 + e) * TT + tt) * 512 + n];
            }
            float q1 = qs[n], q2 = qs[512 + n], q3 = qs[1024 + n], q4 = qs[1536 + n];
            float acc[16];
#pragma unroll
            for (int cc = 0; cc < 16; cc++) {
                int c = c0 + cc;
                acc[cc] = mos[c] + SkUs[c * 5 + 0] + SkUs[c * 5 + 1] * q1
                        + SkUs[c * 5 + 2] * q2 + SkUs[c * 5 + 3] * q3
                        + SkUs[c * 5 + 4] * q4;
            }
#pragma unroll
            for (int j = 0; j < 10; j++) {
                float yj = y[j];
#pragma unroll
                for (int cc = 0; cc < 16; cc++) acc[cc] += yj * S[j * 128 + c0 + cc];
            }
            float* op = out + (size_t)(bt * 512 + n) * 128 + c0;
#pragma unroll
            for (int q4i = 0; q4i < 4; q4i++)
                *(float4*)(op + q4i * 4) = make_float4(acc[q4i * 4], acc[q4i * 4 + 1],
                                                       acc[q4i * 4 + 2], acc[q4i * 4 + 3]);
        }
    }
}

// ---------------- launcher ----------------
extern "C" void kernel_launch(void* const* d_in, const int* in_sizes, int n_in,
                              void* d_out, int out_size) {
    const float* x       = (const float*)d_in[0];
    const float* adj     = (const float*)d_in[1];
    const float* W_start = (const float*)d_in[2];
    const float* b_start = (const float*)d_in[3];
    const float* W_skip  = (const float*)d_in[4];
    const float* b_skip  = (const float*)d_in[5];
    const float* W_gc    = (const float*)d_in[6];
    const float* b_gc    = (const float*)d_in[7];
    const float* gcg     = (const float*)d_in[8];
    const float* gcb     = (const float*)d_in[9];
    const float* gcm     = (const float*)d_in[10];
    const float* gcv     = (const float*)d_in[11];
    const float* bng     = (const float*)d_in[12];
    const float* bnb     = (const float*)d_in[13];
    const float* bnm     = (const float*)d_in[14];
    const float* bnv     = (const float*)d_in[15];
    const float* obg     = (const float*)d_in[16];
    const float* obb     = (const float*)d_in[17];
    const float* obm     = (const float*)d_in[18];
    const float* obv     = (const float*)d_in[19];
    float* out = (float*)d_out;

    k_mega<<<GRID, 256>>>(x, adj, W_start, b_start, W_skip, b_skip, W_gc, b_gc,
                          gcg, gcb, gcm, gcv, bng, bnb, bnm, bnv,
                          obg, obb, obm, obv, out);
    (void)in_sizes; (void)n_in; (void)out_size;
}

// round 14
// speedup vs baseline: 1.2783x; 1.0321x over previous
#include <cuda_runtime.h>
#include <math.h>

#define GRID 444
#define TT 12
#define DD 128
#define NPL (1536 * 512)          // floats per Y plane
#define EPSBN 1e-5f

// ---------------- device scratch ----------------
__device__ float g_Y[5 * NPL];            // planes p=0..4, rows=(b*2+e)*12+t
__device__ float g_A2a[512 * 512];        // A^2 split-K part (k<256)
__device__ float g_A2b[512 * 512];        // A^2 split-K part (k>=256)
__device__ float g_q[5 * 512];            // q_k = 1^T A^k, rows 1..4
__device__ float g_Sfin[10 * DD];
__device__ float g_SkUf[DD * 5];
__device__ float g_mo[DD];
__device__ unsigned g_bcnt = 0u;
__device__ unsigned g_bgen = 0u;

// ---------------- grid-wide barrier (all 444 blocks resident) ----------------
__device__ __forceinline__ void grid_sync() {
    __threadfence();
    __syncthreads();
    if (threadIdx.x == 0) {
        unsigned gen = atomicAdd(&g_bgen, 0u);
        if (atomicAdd(&g_bcnt, 1u) == (unsigned)GRID - 1u) {
            atomicExch(&g_bcnt, 0u);
            __threadfence();
            atomicAdd(&g_bgen, 1u);
        } else {
            while (atomicAdd(&g_bgen, 0u) == gen) __nanosleep(128);
        }
        __threadfence();
    }
    __syncthreads();
}

// ---------------- 64x64 double-buffered SGEMM tile (optional summed operands)
__device__ __forceinline__ void sgemm64(float* SM,
        const float* __restrict__ A, const float* __restrict__ Ab,
        const float* __restrict__ B, const float* __restrict__ Bb,
        float* __restrict__ C, int m0, int n0, int k0, int nk)
{
    float (*As)[16][64] = (float(*)[16][64])SM;
    float (*Bs)[16][64] = (float(*)[16][64])(SM + 2048);
    int tid = threadIdx.x;
    int tx = tid & 15, ty = tid >> 4;
    int ar = tid >> 2, ak = (tid & 3) << 2;
    int bk = tid >> 4, bc = (tid & 15) << 2;
    const float* Ap = A + (size_t)(m0 + ar) * 512 + k0 + ak;
    const float* Bp = B + (size_t)(k0 + bk) * 512 + n0 + bc;
    ptrdiff_t dA = Ab ? (Ab - A) : 0;
    ptrdiff_t dB = Bb ? (Bb - B) : 0;

    float4 av = *(const float4*)Ap;
    if (Ab) { float4 e = *(const float4*)(Ap + dA);
              av.x += e.x; av.y += e.y; av.z += e.z; av.w += e.w; }
    float4 bv = *(const float4*)Bp;
    if (Bb) { float4 e = *(const float4*)(Bp + dB);
              bv.x += e.x; bv.y += e.y; bv.z += e.z; bv.w += e.w; }
    As[0][ak + 0][ar] = av.x; As[0][ak + 1][ar] = av.y;
    As[0][ak + 2][ar] = av.z; As[0][ak + 3][ar] = av.w;
    *(float4*)&Bs[0][bk][bc] = bv;
    __syncthreads();

    float acc[4][4] = {};
#pragma unroll 1
    for (int kt = 0; kt < nk; kt++) {
        int cur = kt & 1;
        if (kt < nk - 1) {
            av = *(const float4*)(Ap + (kt + 1) * 16);
            if (Ab) { float4 e = *(const float4*)(Ap + (kt + 1) * 16 + dA);
                      av.x += e.x; av.y += e.y; av.z += e.z; av.w += e.w; }
            bv = *(const float4*)(Bp + (size_t)(kt + 1) * 16 * 512);
            if (Bb) { float4 e = *(const float4*)(Bp + (size_t)(kt + 1) * 16 * 512 + dB);
                      bv.x += e.x; bv.y += e.y; bv.z += e.z; bv.w += e.w; }
        }
#pragma unroll
        for (int k = 0; k < 16; k++) {
            float a[4], b[4];
            *(float4*)a = *(const float4*)&As[cur][k][ty * 4];
            *(float4*)b = *(const float4*)&Bs[cur][k][tx * 4];
#pragma unroll
            for (int i = 0; i < 4; i++)
#pragma unroll
                for (int j = 0; j < 4; j++) acc[i][j] += a[i] * b[j];
        }
        if (kt < nk - 1) {
            int nx = cur ^ 1;
            As[nx][ak + 0][ar] = av.x; As[nx][ak + 1][ar] = av.y;
            As[nx][ak + 2][ar] = av.z; As[nx][ak + 3][ar] = av.w;
            *(float4*)&Bs[nx][bk][bc] = bv;
            __syncthreads();
        }
    }
#pragma unroll
    for (int i = 0; i < 4; i++) {
        float4 v = make_float4(acc[i][0], acc[i][1], acc[i][2], acc[i][3]);
        *(float4*)(C + (size_t)(m0 + ty * 4 + i) * 512 + n0 + tx * 4) = v;
    }
}

// ---------------- column-sum / q^T M tasks (64 cols per task) ----------------
__device__ void colsum_task(float* SM, const float* __restrict__ M,
                            const float* __restrict__ M2, float* dst, int blk) {
    int tid = threadIdx.x;
    int col = blk * 64 + (tid & 63);
    int rs = tid >> 6;
    float a = 0.f;
#pragma unroll 8
    for (int v = rs * 128; v < rs * 128 + 128; v++) {
        a += M[(size_t)v * 512 + col];
        if (M2) a += M2[(size_t)v * 512 + col];
    }
    SM[512 + tid] = a;
    __syncthreads();
    if (rs == 0)
        dst[col] = SM[512 + tid] + SM[512 + tid + 64]
                 + SM[512 + tid + 128] + SM[512 + tid + 192];
}

__device__ void vecmat_task(float* SM, const float* __restrict__ qsrc,
                            const float* __restrict__ M, const float* __restrict__ M2,
                            float* dst, int blk) {
    int tid = threadIdx.x;
    for (int i = tid; i < 512; i += 256) SM[i] = qsrc[i];
    __syncthreads();
    int col = blk * 64 + (tid & 63);
    int rs = tid >> 6;
    float a = 0.f;
#pragma unroll 8
    for (int v = rs * 128; v < rs * 128 + 128; v++)
        a += SM[v] * (M[(size_t)v * 512 + col] + M2[(size_t)v * 512 + col]);
    SM[512 + tid] = a;
    __syncthreads();
    if (rs == 0)
        dst[col] = SM[512 + tid] + SM[512 + tid + 64]
                 + SM[512 + tid + 128] + SM[512 + tid + 192];
}

// ---------------- warp-cooperative composite chain (1 block) ----------------
__device__ void composite_run(float* SM,
    const float* __restrict__ W_start, const float* __restrict__ b_start,
    const float* __restrict__ W_skip,  const float* __restrict__ b_skip,
    const float* __restrict__ W_gc,    const float* __restrict__ b_gc,
    const float* __restrict__ gcg, const float* __restrict__ gcb,
    const float* __restrict__ gcm, const float* __restrict__ gcv,
    const float* __restrict__ bng, const float* __restrict__ bnb,
    const float* __restrict__ bnm, const float* __restrict__ bnv,
    const float* __restrict__ obg, const float* __restrict__ obb,
    const float* __restrict__ obm, const float* __restrict__ obv)
{
    float* Sg  = SM;              // 384*15 = 5760
    float* Ca  = SM + 5760;       // 1280  [p*256 + c*2 + e]
    float* Ua  = Ca + 1280;       // 640   [c*5 + k]
    float* SkC = Ua + 640;        // 1280
    float* SkU = SkC + 1280;      // 640
    int tid = threadIdx.x, wid = tid >> 5, lane = tid & 31;

    for (int i = tid; i < 1280; i += 256) { Ca[i] = 0.f; SkC[i] = 0.f; }
    for (int i = tid; i < 640;  i += 256) { Ua[i] = 0.f; SkU[i] = 0.f; }
    __syncthreads();
    if (tid < 128) {
        Ca[tid * 2 + 0] = W_start[tid * 2 + 0];
        Ca[tid * 2 + 1] = W_start[tid * 2 + 1];
        Ua[tid * 5] = b_start[tid];
    }
    __syncthreads();

    for (int s = 0; s < 5; s++) {
        int i = s >> 1;
        int isgc = s & 1;
        int jmax = isgc ? 384 : 128;
        for (int j = tid; j < jmax; j += 256) {
            int sub = j >> 7, m = j & 127;
#pragma unroll
            for (int v = 0; v < 10; v++) {
                int p = (v >> 1) - sub;
                Sg[j * 15 + v] = (p >= 0) ? Ca[p * 256 + m * 2 + (v & 1)] : 0.f;
            }
#pragma unroll
            for (int k = 0; k < 5; k++) {
                int kk = k - sub;
                Sg[j * 15 + 10 + k] = (kk >= 0) ? Ua[m * 5 + kk] : 0.f;
            }
        }
        __syncthreads();
        const float* Wb = isgc ? (W_gc + i * 128 * 384) : (W_skip + i * 128 * 128);
        for (int ci = 0; ci < 16; ci++) {
            int c = wid * 16 + ci;
            const float* Wr = Wb + (size_t)c * jmax;
            float acc[15];
#pragma unroll
            for (int v = 0; v < 15; v++) acc[v] = 0.f;
            if (isgc) {
                float w[12];
#pragma unroll
                for (int u = 0; u < 12; u++) w[u] = Wr[lane + u * 32];
#pragma unroll
                for (int u = 0; u < 12; u++) {
                    const float* sp = &Sg[(lane + u * 32) * 15];
#pragma unroll
                    for (int v = 0; v < 15; v++) acc[v] += w[u] * sp[v];
                }
            } else {
                float w[4];
#pragma unroll
                for (int u = 0; u < 4; u++) w[u] = Wr[lane + u * 32];
#pragma unroll
                for (int u = 0; u < 4; u++) {
                    const float* sp = &Sg[(lane + u * 32) * 15];
#pragma unroll
                    for (int v = 0; v < 15; v++) acc[v] += w[u] * sp[v];
                }
            }
            float mine = 0.f;
#pragma unroll
            for (int v = 0; v < 15; v++) {
                float r = acc[v];
#pragma unroll
                for (int o = 16; o; o >>= 1) r += __shfl_xor_sync(0xffffffffu, r, o);
                if (lane == v) mine = r;
            }
            if (!isgc) {
                if (lane < 10) {
                    SkC[(lane >> 1) * 256 + c * 2 + (lane & 1)] += mine;
                } else if (lane < 15) {
                    int kk = lane - 10;
                    SkU[c * 5 + kk] += mine + ((kk == 0) ? b_skip[i * 128 + c] : 0.f);
                }
            } else if (lane < 15) {
                float ig = gcg[i * 128 + c] * rsqrtf(gcv[i * 128 + c] + EPSBN);
                float mg = gcb[i * 128 + c] - gcm[i * 128 + c] * ig;
                float ib = bng[i * 128 + c] * rsqrtf(bnv[i * 128 + c] + EPSBN);
                float mb = bnb[i * 128 + c] - bnm[i * 128 + c] * ib;
                if (lane < 10) {
                    int p = lane >> 1, e = lane & 1, id = p * 256 + c * 2 + e;
                    Ca[id] = ib * (ig * mine + Ca[id]);
                } else {
                    int kk = lane - 10, id = c * 5 + kk;
                    float h = mine + ((kk == 0) ? b_gc[i * 128 + c] : 0.f);
                    Ua[id] = ib * (ig * h + ((kk == 0) ? mg : 0.f) + Ua[id])
                           + ((kk == 0) ? mb : 0.f);
                }
            }
        }
        __syncthreads();
    }
    if (tid < 128) {
        int c = tid;
        float io = obg[c] * rsqrtf(obv[c] + EPSBN);
        float mo = obb[c] - obm[c] * io;
#pragma unroll
        for (int v = 0; v < 10; v++)
            g_Sfin[v * 128 + c] = io * SkC[(v >> 1) * 256 + c * 2 + (v & 1)];
#pragma unroll
        for (int k = 0; k < 5; k++) g_SkUf[c * 5 + k] = io * SkU[c * 5 + k];
        g_mo[c] = mo;
    }
}

// ---------------- the single persistent kernel ----------------
__global__ void __launch_bounds__(256, 3) k_mega(
    const float* __restrict__ x, const float* __restrict__ adj,
    const float* __restrict__ W_start, const float* __restrict__ b_start,
    const float* __restrict__ W_skip,  const float* __restrict__ b_skip,
    const float* __restrict__ W_gc,    const float* __restrict__ b_gc,
    const float* __restrict__ gcg, const float* __restrict__ gcb,
    const float* __restrict__ gcm, const float* __restrict__ gcv,
    const float* __restrict__ bng, const float* __restrict__ bnb,
    const float* __restrict__ bnm, const float* __restrict__ bnv,
    const float* __restrict__ obg, const float* __restrict__ obb,
    const float* __restrict__ obm, const float* __restrict__ obv,
    float* __restrict__ out)
{
    __shared__ float SM[9600];           // 38.4 KB, union for all phases
    int bid = blockIdx.x, tid = threadIdx.x;

    // ======== P0: transpose(128) | A2 split-K(128) | q1(8) ========
    for (int t = bid; t < 264; t += GRID) {
        __syncthreads();
        if (t < 128) {
            const float* src = x + (size_t)t * 6144;
            for (int i = tid; i < 6144; i += 256) SM[i] = src[i];
            __syncthreads();
            float* dst = g_Y + (size_t)t * 6144;
            for (int i = tid; i < 6144; i += 256) {
                int tt = i >> 9, n = i & 511;
                dst[i] = SM[n * TT + tt];
            }
        } else if (t < 256) {
            int s = (t - 128) >> 6, tile = (t - 128) & 63;
            sgemm64(SM, adj, nullptr, adj, nullptr, s ? g_A2b : g_A2a,
                    (tile >> 3) * 64, (tile & 7) * 64, s * 256, 16);
        } else {
            colsum_task(SM, adj, nullptr, g_q + 512, t - 256);
        }
    }
    grid_sync();

    // ======== P1: Y1(192) | Y2(192) | q2(8) | q3(8) | composite(1) ========
    for (int t = bid; t < 401; t += GRID) {
        __syncthreads();
        if (t < 192) {
            sgemm64(SM, g_Y, nullptr, adj, nullptr, g_Y + NPL,
                    (t >> 3) * 64, (t & 7) * 64, 0, 32);
        } else if (t < 384) {
            int u = t - 192;
            sgemm64(SM, g_Y, nullptr, g_A2a, g_A2b, g_Y + 2 * NPL,
                    (u >> 3) * 64, (u & 7) * 64, 0, 32);
        } else if (t < 392) {
            colsum_task(SM, g_A2a, g_A2b, g_q + 1024, t - 384);
        } else if (t < 400) {
            vecmat_task(SM, g_q + 512, g_A2a, g_A2b, g_q + 1536, t - 392);
        } else {
            composite_run(SM, W_start, b_start, W_skip, b_skip, W_gc, b_gc,
                          gcg, gcb, gcm, gcv, bng, bnb, bnm, bnv,
                          obg, obb, obm, obv);
        }
    }
    grid_sync();

    // ======== P2: Y3=Y1*A2(192) | Y4=Y2*A2(192) | q4(8) ========
    for (int t = bid; t < 392; t += GRID) {
        __syncthreads();
        if (t < 192) {
            sgemm64(SM, g_Y + NPL, nullptr, g_A2a, g_A2b, g_Y + 3 * NPL,
                    (t >> 3) * 64, (t & 7) * 64, 0, 32);
        } else if (t < 384) {
            int u = t - 192;
            sgemm64(SM, g_Y + 2 * NPL, nullptr, g_A2a, g_A2b, g_Y + 4 * NPL,
                    (u >> 3) * 64, (u & 7) * 64, 0, 32);
        } else {
            vecmat_task(SM, g_q + 1024, g_A2a, g_A2b, g_q + 2048, t - 384);
        }
    }
    grid_sync();

    // ======== P3: final expansion (12288 tiles of 32 nodes) ========
    {
        float* S    = SM;            // 1280
        float* SkUs = SM + 1280;     // 640
        float* mos  = SM + 1920;     // 128
        float* qs   = SM + 2048;     // 2048
        for (int i = tid; i < 1280; i += 256) S[i] = g_Sfin[i];
        for (int i = tid; i < 640;  i += 256) SkUs[i] = g_SkUf[i];
        if (tid < 128) mos[tid] = g_mo[tid];
        for (int i = tid; i < 2048; i += 256) qs[i] = g_q[512 + i];
        __syncthreads();
        int i = tid >> 3, c0 = (tid & 7) * 16;
        for (int task = bid; task < 12288; task += GRID) {
            int nt = task & 15, bt = task >> 4;
            int b = bt / TT, tt = bt - b * TT;
            int n = nt * 32 + i;
            float y[10];
#pragma unroll
            for (int j = 0; j < 10; j++) {
                int p = j >> 1, e = j & 1;
                y[j] = g_Y[(size_t)p * NPL + (size_t)((b * 2 + e) * TT + tt) * 512 + n];
            }
            float q1 = qs[n], q2 = qs[512 + n], q3 = qs[1024 + n], q4 = qs[1536 + n];
            float acc[16];
#pragma unroll
            for (int cc = 0; cc < 16; cc++) {
                int c = c0 + cc;
                acc[cc] = mos[c] + SkUs[c * 5 + 0] + SkUs[c * 5 + 1] * q1
                        + SkUs[c * 5 + 2] * q2 + SkUs[c * 5 + 3] * q3
                        + SkUs[c * 5 + 4] * q4;
            }
#pragma unroll
            for (int j = 0; j < 10; j++) {
                float yj = y[j];
#pragma unroll
                for (int cc = 0; cc < 16; cc++) acc[cc] += yj * S[j * 128 + c0 + cc];
            }
            float* op = out + (size_t)(bt * 512 + n) * 128 + c0;
#pragma unroll
            for (int q4i = 0; q4i < 4; q4i++)
                *(float4*)(op + q4i * 4) = make_float4(acc[q4i * 4], acc[q4i * 4 + 1],
                                                       acc[q4i * 4 + 2], acc[q4i * 4 + 3]);
        }
    }
}

// ---------------- launcher ----------------
extern "C" void kernel_launch(void* const* d_in, const int* in_sizes, int n_in,
                              void* d_out, int out_size) {
    const float* x       = (const float*)d_in[0];
    const float* adj     = (const float*)d_in[1];
    const float* W_start = (const float*)d_in[2];
    const float* b_start = (const float*)d_in[3];
    const float* W_skip  = (const float*)d_in[4];
    const float* b_skip  = (const float*)d_in[5];
    const float* W_gc    = (const float*)d_in[6];
    const float* b_gc    = (const float*)d_in[7];
    const float* gcg     = (const float*)d_in[8];
    const float* gcb     = (const float*)d_in[9];
    const float* gcm     = (const float*)d_in[10];
    const float* gcv     = (const float*)d_in[11];
    const float* bng     = (const float*)d_in[12];
    const float* bnb     = (const float*)d_in[13];
    const float* bnm     = (const float*)d_in[14];
    const float* bnv     = (const float*)d_in[15];
    const float* obg     = (const float*)d_in[16];
    const float* obb     = (const float*)d_in[17];
    const float* obm     = (const float*)d_in[18];
    const float* obv     = (const float*)d_in[19];
    float* out = (float*)d_out;

    k_mega<<<GRID, 256>>>(x, adj, W_start, b_start, W_skip, b_skip, W_gc, b_gc,
                          gcg, gcb, gcm, gcv, bng, bnb, bnm, bnv,
                          obg, obb, obm, obv, out);
    (void)in_sizes; (void)n_in; (void)out_size;
}

// round 15
// speedup vs baseline: 1.5434x; 1.2074x over previous
#include <cuda_runtime.h>
#include <math.h>

#define GRID 296
#define TT 12
#define DD 128
#define NPL (1536 * 512)
#define MSZ (512 * 512)
#define EPSBN 1e-5f

__device__ __align__(16) float g_Y0[NPL];
__device__ __align__(16) float g_Ys[2 * NPL];     // solid Y1, Y2
__device__ __align__(16) float g_Hp[6 * NPL];     // 3 K-parts x 2 planes
__device__ __align__(16) float g_A2[MSZ];
__device__ __align__(16) float g_A2p[2 * MSZ];
__device__ __align__(16) float g_q[5 * 512];
__device__ float g_Sfin[10 * DD];
__device__ float g_SkUf[DD * 5];
__device__ float g_mo[DD];
__device__ unsigned g_bcnt = 0u;
__device__ unsigned g_bgen = 0u;

__device__ __forceinline__ void grid_sync() {
    __threadfence();
    __syncthreads();
    if (threadIdx.x == 0) {
        unsigned gen = atomicAdd(&g_bgen, 0u);
        if (atomicAdd(&g_bcnt, 1u) == (unsigned)GRID - 1u) {
            atomicExch(&g_bcnt, 0u);
            __threadfence();
            atomicAdd(&g_bgen, 1u);
        } else {
            while (atomicAdd(&g_bgen, 0u) == gen) __nanosleep(128);
        }
        __threadfence();
    }
    __syncthreads();
}

// ------- 128x128 SGEMM tile, 8x8/thread, reg-prefetch, single smem buffer ----
__device__ __forceinline__ void sgemm128(float* SMb,
    const float* __restrict__ A, const float* __restrict__ B, float* __restrict__ C,
    int m0, int n0, int k0, int nkt)
{
    float (*As)[128] = (float(*)[128])SMb;            // As[k][m]
    float (*Bs)[128] = (float(*)[128])(SMb + 2048);   // Bs[k][n]
    int tid = threadIdx.x;
    int tx = tid & 15, ty = tid >> 4;
    int ar0 = tid >> 1, ak0 = (tid & 1) << 3;         // A: 2 float4 per thread
    const float* Ap = A + (size_t)(m0 + ar0) * 512 + k0 + ak0;
    int bk = tid >> 5, bc = (tid & 31) << 2;          // B: 2 float4 per thread
    const float* Bp0 = B + (size_t)(k0 + bk) * 512 + n0 + bc;
    const float* Bp1 = Bp0 + (size_t)8 * 512;

    float4 a0 = *(const float4*)Ap;
    float4 a1 = *(const float4*)(Ap + 4);
    float4 b0 = *(const float4*)Bp0;
    float4 b1 = *(const float4*)Bp1;

    float acc[8][8];
#pragma unroll
    for (int i = 0; i < 8; i++)
#pragma unroll
        for (int j = 0; j < 8; j++) acc[i][j] = 0.f;

#pragma unroll 1
    for (int kt = 0; kt < nkt; kt++) {
        As[ak0 + 0][ar0] = a0.x; As[ak0 + 1][ar0] = a0.y;
        As[ak0 + 2][ar0] = a0.z; As[ak0 + 3][ar0] = a0.w;
        As[ak0 + 4][ar0] = a1.x; As[ak0 + 5][ar0] = a1.y;
        As[ak0 + 6][ar0] = a1.z; As[ak0 + 7][ar0] = a1.w;
        *(float4*)&Bs[bk][bc] = b0;
        *(float4*)&Bs[bk + 8][bc] = b1;
        __syncthreads();
        if (kt + 1 < nkt) {
            a0 = *(const float4*)(Ap + (kt + 1) * 16);
            a1 = *(const float4*)(Ap + (kt + 1) * 16 + 4);
            b0 = *(const float4*)(Bp0 + (size_t)(kt + 1) * 16 * 512);
            b1 = *(const float4*)(Bp1 + (size_t)(kt + 1) * 16 * 512);
        }
#pragma unroll
        for (int k = 0; k < 16; k++) {
            float a[8], b[8];
            *(float4*)&a[0] = *(const float4*)&As[k][ty * 8];
            *(float4*)&a[4] = *(const float4*)&As[k][ty * 8 + 4];
            *(float4*)&b[0] = *(const float4*)&Bs[k][tx * 8];
            *(float4*)&b[4] = *(const float4*)&Bs[k][tx * 8 + 4];
#pragma unroll
            for (int i = 0; i < 8; i++)
#pragma unroll
                for (int j = 0; j < 8; j++) acc[i][j] += a[i] * b[j];
        }
        __syncthreads();
    }
#pragma unroll
    for (int i = 0; i < 8; i++) {
        float* cp = C + (size_t)(m0 + ty * 8 + i) * 512 + n0 + tx * 8;
        *(float4*)cp = make_float4(acc[i][0], acc[i][1], acc[i][2], acc[i][3]);
        *(float4*)(cp + 4) = make_float4(acc[i][4], acc[i][5], acc[i][6], acc[i][7]);
    }
}

// ------------- colsum / vecmat (64 cols per task) -------------
__device__ void colsum_task(float* SMf, const float* __restrict__ M, float* dst, int blk) {
    int tid = threadIdx.x;
    int col = blk * 64 + (tid & 63);
    int rs = tid >> 6;
    float a = 0.f;
#pragma unroll 8
    for (int v = rs * 128; v < rs * 128 + 128; v++) a += M[(size_t)v * 512 + col];
    SMf[tid] = a;
    __syncthreads();
    if (rs == 0)
        dst[col] = SMf[tid] + SMf[tid + 64] + SMf[tid + 128] + SMf[tid + 192];
}
__device__ void vecmat_task(float* SMf, const float* __restrict__ qsrc,
                            const float* __restrict__ M, float* dst, int blk) {
    int tid = threadIdx.x;
    for (int i = tid; i < 512; i += 256) SMf[i] = qsrc[i];
    __syncthreads();
    int col = blk * 64 + (tid & 63);
    int rs = tid >> 6;
    float a = 0.f;
#pragma unroll 8
    for (int v = rs * 128; v < rs * 128 + 128; v++) a += SMf[v] * M[(size_t)v * 512 + col];
    SMf[512 + tid] = a;
    __syncthreads();
    if (rs == 0)
        dst[col] = SMf[512 + tid] + SMf[512 + tid + 64]
                 + SMf[512 + tid + 128] + SMf[512 + tid + 192];
}

// ------------- warp-cooperative composite chain (unchanged from R12) ---------
__device__ void composite_run(float* SM,
    const float* __restrict__ W_start, const float* __restrict__ b_start,
    const float* __restrict__ W_skip,  const float* __restrict__ b_skip,
    const float* __restrict__ W_gc,    const float* __restrict__ b_gc,
    const float* __restrict__ gcg, const float* __restrict__ gcb,
    const float* __restrict__ gcm, const float* __restrict__ gcv,
    const float* __restrict__ bng, const float* __restrict__ bnb,
    const float* __restrict__ bnm, const float* __restrict__ bnv,
    const float* __restrict__ obg, const float* __restrict__ obb,
    const float* __restrict__ obm, const float* __restrict__ obv)
{
    float* Sg  = SM;
    float* Ca  = SM + 5760;
    float* Ua  = Ca + 1280;
    float* SkC = Ua + 640;
    float* SkU = SkC + 1280;
    int tid = threadIdx.x, wid = tid >> 5, lane = tid & 31;

    for (int i = tid; i < 1280; i += 256) { Ca[i] = 0.f; SkC[i] = 0.f; }
    for (int i = tid; i < 640;  i += 256) { Ua[i] = 0.f; SkU[i] = 0.f; }
    __syncthreads();
    if (tid < 128) {
        Ca[tid * 2 + 0] = W_start[tid * 2 + 0];
        Ca[tid * 2 + 1] = W_start[tid * 2 + 1];
        Ua[tid * 5] = b_start[tid];
    }
    __syncthreads();
    for (int s = 0; s < 5; s++) {
        int i = s >> 1, isgc = s & 1;
        int jmax = isgc ? 384 : 128;
        for (int j = tid; j < jmax; j += 256) {
            int sub = j >> 7, m = j & 127;
#pragma unroll
            for (int v = 0; v < 10; v++) {
                int p = (v >> 1) - sub;
                Sg[j * 15 + v] = (p >= 0) ? Ca[p * 256 + m * 2 + (v & 1)] : 0.f;
            }
#pragma unroll
            for (int k = 0; k < 5; k++) {
                int kk = k - sub;
                Sg[j * 15 + 10 + k] = (kk >= 0) ? Ua[m * 5 + kk] : 0.f;
            }
        }
        __syncthreads();
        const float* Wb = isgc ? (W_gc + i * 128 * 384) : (W_skip + i * 128 * 128);
        for (int ci = 0; ci < 16; ci++) {
            int c = wid * 16 + ci;
            const float* Wr = Wb + (size_t)c * jmax;
            float acc[15];
#pragma unroll
            for (int v = 0; v < 15; v++) acc[v] = 0.f;
            int nu = isgc ? 12 : 4;
            for (int u = 0; u < nu; u++) {
                float w = Wr[lane + u * 32];
                const float* sp = &Sg[(lane + u * 32) * 15];
#pragma unroll
                for (int v = 0; v < 15; v++) acc[v] += w * sp[v];
            }
            float mine = 0.f;
#pragma unroll
            for (int v = 0; v < 15; v++) {
                float r = acc[v];
#pragma unroll
                for (int o = 16; o; o >>= 1) r += __shfl_xor_sync(0xffffffffu, r, o);
                if (lane == v) mine = r;
            }
            if (!isgc) {
                if (lane < 10) SkC[(lane >> 1) * 256 + c * 2 + (lane & 1)] += mine;
                else if (lane < 15) {
                    int kk = lane - 10;
                    SkU[c * 5 + kk] += mine + ((kk == 0) ? b_skip[i * 128 + c] : 0.f);
                }
            } else if (lane < 15) {
                float ig = gcg[i * 128 + c] * rsqrtf(gcv[i * 128 + c] + EPSBN);
                float mg = gcb[i * 128 + c] - gcm[i * 128 + c] * ig;
                float ib = bng[i * 128 + c] * rsqrtf(bnv[i * 128 + c] + EPSBN);
                float mb = bnb[i * 128 + c] - bnm[i * 128 + c] * ib;
                if (lane < 10) {
                    int p = lane >> 1, e = lane & 1, id = p * 256 + c * 2 + e;
                    Ca[id] = ib * (ig * mine + Ca[id]);
                } else {
                    int kk = lane - 10, id = c * 5 + kk;
                    float h = mine + ((kk == 0) ? b_gc[i * 128 + c] : 0.f);
                    Ua[id] = ib * (ig * h + ((kk == 0) ? mg : 0.f) + Ua[id])
                           + ((kk == 0) ? mb : 0.f);
                }
            }
        }
        __syncthreads();
    }
    if (tid < 128) {
        int c = tid;
        float io = obg[c] * rsqrtf(obv[c] + EPSBN);
#pragma unroll
        for (int v = 0; v < 10; v++)
            g_Sfin[v * 128 + c] = io * SkC[(v >> 1) * 256 + c * 2 + (v & 1)];
#pragma unroll
        for (int k = 0; k < 5; k++) g_SkUf[c * 5 + k] = io * SkU[c * 5 + k];
        g_mo[c] = obb[c] - obm[c] * io;
    }
}

// ---------------- the single persistent kernel ----------------
__global__ void __launch_bounds__(256, 2) k_mega(
    const float* __restrict__ x, const float* __restrict__ adj,
    const float* __restrict__ W_start, const float* __restrict__ b_start,
    const float* __restrict__ W_skip,  const float* __restrict__ b_skip,
    const float* __restrict__ W_gc,    const float* __restrict__ b_gc,
    const float* __restrict__ gcg, const float* __restrict__ gcb,
    const float* __restrict__ gcm, const float* __restrict__ gcv,
    const float* __restrict__ bng, const float* __restrict__ bnb,
    const float* __restrict__ bnm, const float* __restrict__ bnv,
    const float* __restrict__ obg, const float* __restrict__ obb,
    const float* __restrict__ obm, const float* __restrict__ obv,
    float* __restrict__ out)
{
    __shared__ __align__(16) float SM[9600];
    int bid = blockIdx.x, tid = threadIdx.x;

    // ===== P0: transpose(128) | A^2 split-2 (32) | q1(8) | composite(1) =====
    for (int t = bid; t < 169; t += GRID) {
        __syncthreads();
        if (t < 128) {
            const float* src = x + (size_t)t * 6144;
            for (int i = tid; i < 6144; i += 256) SM[i] = src[i];
            __syncthreads();
            float* dst = g_Y0 + (size_t)t * 6144;
            for (int i = tid; i < 6144; i += 256) {
                int tt = i >> 9, n = i & 511;
                dst[i] = SM[n * TT + tt];
            }
        } else if (t < 160) {
            int ti = t - 128, kh = ti >> 4, tile = ti & 15;
            sgemm128(SM, adj, adj, g_A2p + (size_t)kh * MSZ,
                     (tile >> 2) * 128, (tile & 3) * 128, kh * 256, 16);
        } else if (t < 168) {
            colsum_task(SM, adj, g_q + 512, t - 160);
        } else {
            composite_run(SM, W_start, b_start, W_skip, b_skip, W_gc, b_gc,
                          gcg, gcb, gcm, gcv, bng, bnb, bnm, bnv,
                          obg, obb, obm, obv);
        }
    }
    grid_sync();

    // ===== P0b: solidify A^2 (16 tasks) =====
    for (int t = bid; t < 16; t += GRID) {
        const float4* pa = (const float4*)g_A2p + (size_t)t * 4096;
        const float4* pb = pa + MSZ / 4;
        float4* pd = (float4*)g_A2 + (size_t)t * 4096;
        for (int i = tid; i < 4096; i += 256) {
            float4 a = pa[i], b = pb[i];
            pd[i] = make_float4(a.x + b.x, a.y + b.y, a.z + b.z, a.w + b.w);
        }
    }
    grid_sync();

    // ===== P1: Y1 thirds(144) | Y2 thirds(144) | q2(8) = 296 =====
    for (int t = bid; t < 296; t += GRID) {
        __syncthreads();
        if (t < 288) {
            int plane = t / 144, r = t % 144;
            int kh = r / 48, rr = r % 48;
            sgemm128(SM, g_Y0, plane ? g_A2 : adj,
                     g_Hp + (size_t)kh * (2 * NPL) + (size_t)plane * NPL,
                     (rr >> 2) * 128, (rr & 3) * 128, kh * 176, (kh == 2) ? 10 : 11);
        } else {
            colsum_task(SM, g_A2, g_q + 1024, t - 288);
        }
    }
    grid_sync();

    // ===== P1b: solidify Y1,Y2 (48) | q3(8) | q4(8) = 64 =====
    for (int t = bid; t < 64; t += GRID) {
        __syncthreads();
        if (t < 48) {
            const float4* p0 = (const float4*)g_Hp + (size_t)t * 8192;
            const float4* p1 = p0 + (2 * NPL) / 4;
            const float4* p2 = p1 + (2 * NPL) / 4;
            float4* pd = (float4*)g_Ys + (size_t)t * 8192;
            for (int i = tid; i < 8192; i += 256) {
                float4 a = p0[i], b = p1[i], c = p2[i];
                pd[i] = make_float4(a.x + b.x + c.x, a.y + b.y + c.y,
                                    a.z + b.z + c.z, a.w + b.w + c.w);
            }
        } else if (t < 56) {
            vecmat_task(SM, g_q + 512, g_A2, g_q + 1536, t - 48);
        } else {
            vecmat_task(SM, g_q + 1024, g_A2, g_q + 2048, t - 56);
        }
    }
    grid_sync();

    // ===== P2: Y3 thirds(144) | Y4 thirds(144) = 288 =====
    for (int t = bid; t < 288; t += GRID) {
        __syncthreads();
        int plane = t / 144, r = t % 144;
        int kh = r / 48, rr = r % 48;
        sgemm128(SM, g_Ys + (size_t)plane * NPL, g_A2,
                 g_Hp + (size_t)kh * (2 * NPL) + (size_t)plane * NPL,
                 (rr >> 2) * 128, (rr & 3) * 128, kh * 176, (kh == 2) ? 10 : 11);
    }
    grid_sync();

    // ===== P3: final expansion (12288 tiles of 32 nodes) =====
    {
        float* S    = SM;            // 1280
        float* SkUs = SM + 1280;     // 640
        float* mos  = SM + 1920;     // 128
        float* qs   = SM + 2048;     // 2048
        for (int i = tid; i < 1280; i += 256) S[i] = g_Sfin[i];
        for (int i = tid; i < 640;  i += 256) SkUs[i] = g_SkUf[i];
        if (tid < 128) mos[tid] = g_mo[tid];
        for (int i = tid; i < 2048; i += 256) qs[i] = g_q[512 + i];
        __syncthreads();
        int i = tid >> 3, c0 = (tid & 7) * 16;
        for (int task = bid; task < 12288; task += GRID) {
            int nt = task & 15, bt = task >> 4;
            int b = bt / TT, tt = bt - b * TT;
            int n = nt * 32 + i;
            size_t ro = (size_t)((b * 2) * TT + tt) * 512 + n;       // e=0 row
            size_t r1 = ro + (size_t)TT * 512;                       // e=1 row
            float y[10];
            y[0] = g_Y0[ro]; y[1] = g_Y0[r1];
            y[2] = g_Ys[ro]; y[3] = g_Ys[r1];
            y[4] = g_Ys[NPL + ro]; y[5] = g_Ys[NPL + r1];
            y[6] = g_Hp[ro] + g_Hp[2 * NPL + ro] + g_Hp[4 * NPL + ro];
            y[7] = g_Hp[r1] + g_Hp[2 * NPL + r1] + g_Hp[4 * NPL + r1];
            y[8] = g_Hp[NPL + ro] + g_Hp[3 * NPL + ro] + g_Hp[5 * NPL + ro];
            y[9] = g_Hp[NPL + r1] + g_Hp[3 * NPL + r1] + g_Hp[5 * NPL + r1];
            float q1 = qs[n], q2 = qs[512 + n], q3 = qs[1024 + n], q4 = qs[1536 + n];
            float acc[16];
#pragma unroll
            for (int cc = 0; cc < 16; cc++) {
                int c = c0 + cc;
                acc[cc] = mos[c] + SkUs[c * 5 + 0] + SkUs[c * 5 + 1] * q1
                        + SkUs[c * 5 + 2] * q2 + SkUs[c * 5 + 3] * q3
                        + SkUs[c * 5 + 4] * q4;
            }
#pragma unroll
            for (int j = 0; j < 10; j++) {
                float yj = y[j];
#pragma unroll
                for (int cc = 0; cc < 16; cc++) acc[cc] += yj * S[j * 128 + c0 + cc];
            }
            float* op = out + (size_t)(bt * 512 + n) * 128 + c0;
#pragma unroll
            for (int q4i = 0; q4i < 4; q4i++)
                *(float4*)(op + q4i * 4) = make_float4(acc[q4i * 4], acc[q4i * 4 + 1],
                                                       acc[q4i * 4 + 2], acc[q4i * 4 + 3]);
        }
    }
}

extern "C" void kernel_launch(void* const* d_in, const int* in_sizes, int n_in,
                              void* d_out, int out_size) {
    const float* x       = (const float*)d_in[0];
    const float* adj     = (const float*)d_in[1];
    const float* W_start = (const float*)d_in[2];
    const float* b_start = (const float*)d_in[3];
    const float* W_skip  = (const float*)d_in[4];
    const float* b_skip  = (const float*)d_in[5];
    const float* W_gc    = (const float*)d_in[6];
    const float* b_gc    = (const float*)d_in[7];
    const float* gcg     = (const float*)d_in[8];
    const float* gcb     = (const float*)d_in[9];
    const float* gcm     = (const float*)d_in[10];
    const float* gcv     = (const float*)d_in[11];
    const float* bng     = (const float*)d_in[12];
    const float* bnb     = (const float*)d_in[13];
    const float* bnm     = (const float*)d_in[14];
    const float* bnv     = (const float*)d_in[15];
    const float* obg     = (const float*)d_in[16];
    const float* obb     = (const float*)d_in[17];
    const float* obm     = (const float*)d_in[18];
    const float* obv     = (const float*)d_in[19];
    float* out = (float*)d_out;

    k_mega<<<GRID, 256>>>(x, adj, W_start, b_start, W_skip, b_skip, W_gc, b_gc,
                          gcg, gcb, gcm, gcv, bng, bnb, bnm, bnv,
                          obg, obb, obm, obv, out);
    (void)in_sizes; (void)n_in; (void)out_size;
}